// round 13
// baseline (speedup 1.0000x reference)
#include <cuda_runtime.h>

// GeneratorCell: B=128, M=32 queue rows, N=64 strokes, K=2048 stroke length
// One CTA per batch, 192 threads, ONE barrier:
//   every warp redundantly computes conv+GRU for all 64 strokes (lane l -> strokes
//   2l, 2l+1), giving each lane exactly the ht4 slice its matvec rows need.
#define Bn 128
#define Mn 32
#define Nn 64
#define Kn 2048
#define NT 192                     // 6 warps
#define Cn 11                      // 192*11 = 2112 = N + M*N
#define PAD 72                     // bottom zero pad (even, >=66: FIR reads to p0-66)
#define EMB_SZ (PAD + Kn + 64)     // ull elements

typedef unsigned long long ull;

__device__ __forceinline__ float sigmoidf_(float x) { return 1.0f / (1.0f + __expf(-x)); }
__device__ __forceinline__ float tanhf_(float x) {   // fast tanh via MUFU exp (err ~1e-6)
    float e = __expf(2.0f * x);
    return 1.0f - 2.0f / (e + 1.0f);
}

__device__ __forceinline__ ull pack2(float x, float y) {
    ull r; asm("mov.b64 %0, {%1,%2};" : "=l"(r) : "f"(x), "f"(y)); return r;
}
__device__ __forceinline__ void unpack2(ull v, float& x, float& y) {
    asm("mov.b64 {%0,%1}, %2;" : "=f"(x), "=f"(y) : "l"(v));
}
__device__ __forceinline__ ull ffma2(ull a, ull b, ull c) {   // packed f32x2 FMA (sm_100+)
    ull d; asm("fma.rn.f32x2 %0, %1, %2, %3;" : "=l"(d) : "l"(a), "l"(b), "l"(c)); return d;
}

__global__ __launch_bounds__(NT) void gen_cell_kernel(
    const float* __restrict__ qt1,      // [B, M, N, 2]
    const float* __restrict__ ht1,      // [B, N, 2]
    const float* __restrict__ zt,       // [B, N]
    const float* __restrict__ alpha_t,  // [B, N]
    const float* __restrict__ conv_w,   // [2, 2, M+1, 1]
    const float* __restrict__ conv_b,   // [2]
    const float* __restrict__ W_xr, const float* __restrict__ W_hr, const float* __restrict__ b_r,
    const float* __restrict__ W_xu, const float* __restrict__ W_hu, const float* __restrict__ b_u,
    const float* __restrict__ W_xn, const float* __restrict__ W_hn, const float* __restrict__ b_n,
    const float* __restrict__ lin_w,    // [N, 2N]
    const float* __restrict__ lin_b,    // [N]
    const float* __restrict__ W_emb,    // [K, 2]
    float* __restrict__ out)            // st [B,N,2] | qt [B,M,N,2] | ht [B,N,2]
{
    __shared__ __align__(16) ull s_exy[EMB_SZ];      // interleaved (x,y) emb, zero-padded
    __shared__ ull s_coef2[Nn + 2];                  // coef padded to 66 (= 6*11)

    const int b    = blockIdx.x;
    const int tid  = threadIdx.x;
    const int lane = tid & 31;
    const int wrp  = tid >> 5;
    const float4* qv4 = (const float4*)(qt1 + (size_t)b * Mn * Nn * 2);  // [h*32+l] = strokes 2l,2l+1
    const float2* qf  = (const float2*)(qt1 + (size_t)b * Mn * Nn * 2);

    // ---- emb staging LDGs first (latency overlaps everything below) ----
    const float4* we4 = (const float4*)W_emb;        // 1024 float4
    float4 e0 = we4[tid],       e1 = we4[tid + 192], e2 = we4[tid + 384];
    float4 e3 = we4[tid + 576], e4 = we4[tid + 768];
    float4 e5 = make_float4(0.f, 0.f, 0.f, 0.f);
    if (tid < 64) e5 = we4[tid + 960];

    // zero pads (emb + coef tail)
    if (tid < PAD) s_exy[tid] = 0ULL;
    if (tid < 64)  s_exy[PAD + Kn + tid] = 0ULL;
    if (tid < 2)   s_coef2[Nn + tid] = 0ULL;

    // staged emb store (own LDGs only -> no pre-barrier needed)
    {
        float4* exy4 = (float4*)(s_exy + PAD);
        exy4[tid]       = e0;  exy4[tid + 192] = e1;  exy4[tid + 384] = e2;
        exy4[tid + 576] = e3;  exy4[tid + 768] = e4;
        if (tid < 64) exy4[tid + 960] = e5;
    }

    // ---- conv for strokes sA=2*lane, sB=2*lane+1 (every warp, redundant) ----
    float a0 = 0.f, a1 = 0.f, b0 = 0.f, b1 = 0.f;    // stroke A: out-ch 0/1
    float c0 = 0.f, c1 = 0.f, d0 = 0.f, d1 = 0.f;    // stroke B: out-ch 0/1
    #pragma unroll
    for (int h = 0; h < Mn; h++) {
        const float4 q4 = qv4[h * 32 + lane];        // coalesced; warps 1-5 L1-hit
        const float wa = conv_w[h],      wb = conv_w[33 + h];
        const float wc = conv_w[66 + h], wd = conv_w[99 + h];
        a0 = fmaf(q4.x, wa, a0); a1 = fmaf(q4.y, wb, a1);
        b0 = fmaf(q4.x, wc, b0); b1 = fmaf(q4.y, wd, b1);
        c0 = fmaf(q4.z, wa, c0); c1 = fmaf(q4.w, wb, c1);
        d0 = fmaf(q4.z, wc, d0); d1 = fmaf(q4.w, wd, d1);
    }
    const float4 hv4 = ((const float4*)ht1)[b * 32 + lane];   // ht1 strokes 2l, 2l+1
    // tap 32 (ht1 row) + bias
    const float hA0 = a0 + a1 + conv_b[0] + hv4.x * conv_w[32] + hv4.y * conv_w[65];
    const float hA1 = b0 + b1 + conv_b[1] + hv4.x * conv_w[98] + hv4.y * conv_w[131];
    const float hB0 = c0 + c1 + conv_b[0] + hv4.z * conv_w[32] + hv4.w * conv_w[65];
    const float hB1 = d0 + d1 + conv_b[1] + hv4.z * conv_w[98] + hv4.w * conv_w[131];

    // ---- preload lin_w slices for this warp's 11 matvec rows (hides under GRU) ----
    float4 lv[11];
    {
        const float4* lw4 = (const float4*)lin_w;    // [64 rows][32 float4]
        #pragma unroll
        for (int k = 0; k < 11; k++) {
            const int row = wrp * 11 + k;
            lv[k] = (row < Nn) ? lw4[row * 32 + lane] : make_float4(0.f, 0.f, 0.f, 0.f);
        }
    }

    // ---- GRU for both strokes (registers only) ----
    const float2 zt2 = ((const float2*)zt)[b * 32 + lane];
    const float2 al2 = ((const float2*)alpha_t)[b * 32 + lane];
    float4 ht4;      // (ht[2l].c0, ht[2l].c1, ht[2l+1].c0, ht[2l+1].c1) = ht_flat[4l..4l+3]
    {
        // stroke A
        float x0 = zt2.x, x1 = al2.x;
        float r0 = sigmoidf_(fmaf(x0, W_xr[0], fmaf(x1, W_xr[2], fmaf(hA0, W_hr[0], fmaf(hA1, W_hr[2], b_r[0])))));
        float r1 = sigmoidf_(fmaf(x0, W_xr[1], fmaf(x1, W_xr[3], fmaf(hA0, W_hr[1], fmaf(hA1, W_hr[3], b_r[1])))));
        float u0 = sigmoidf_(fmaf(x0, W_xu[0], fmaf(x1, W_xu[2], fmaf(hA0, W_hu[0], fmaf(hA1, W_hu[2], b_u[0])))));
        float u1 = sigmoidf_(fmaf(x0, W_xu[1], fmaf(x1, W_xu[3], fmaf(hA0, W_hu[1], fmaf(hA1, W_hu[3], b_u[1])))));
        float rh0 = r0 * hA0, rh1 = r1 * hA1;
        float nt0 = tanhf_(fmaf(x0, W_xn[0], fmaf(x1, W_xn[2], fmaf(rh0, W_hn[0], fmaf(rh1, W_hn[2], b_n[0])))));
        float nt1 = tanhf_(fmaf(x0, W_xn[1], fmaf(x1, W_xn[3], fmaf(rh0, W_hn[1], fmaf(rh1, W_hn[3], b_n[1])))));
        ht4.x = u0 * hv4.x + (1.0f - u0) * nt0;
        ht4.y = u1 * hv4.y + (1.0f - u1) * nt1;
        // stroke B
        x0 = zt2.y; x1 = al2.y;
        r0 = sigmoidf_(fmaf(x0, W_xr[0], fmaf(x1, W_xr[2], fmaf(hB0, W_hr[0], fmaf(hB1, W_hr[2], b_r[0])))));
        r1 = sigmoidf_(fmaf(x0, W_xr[1], fmaf(x1, W_xr[3], fmaf(hB0, W_hr[1], fmaf(hB1, W_hr[3], b_r[1])))));
        u0 = sigmoidf_(fmaf(x0, W_xu[0], fmaf(x1, W_xu[2], fmaf(hB0, W_hu[0], fmaf(hB1, W_hu[2], b_u[0])))));
        u1 = sigmoidf_(fmaf(x0, W_xu[1], fmaf(x1, W_xu[3], fmaf(hB0, W_hu[1], fmaf(hB1, W_hu[3], b_u[1])))));
        rh0 = r0 * hB0; rh1 = r1 * hB1;
        nt0 = tanhf_(fmaf(x0, W_xn[0], fmaf(x1, W_xn[2], fmaf(rh0, W_hn[0], fmaf(rh1, W_hn[2], b_n[0])))));
        nt1 = tanhf_(fmaf(x0, W_xn[1], fmaf(x1, W_xn[3], fmaf(rh0, W_hn[1], fmaf(rh1, W_hn[3], b_n[1])))));
        ht4.z = u0 * hv4.z + (1.0f - u0) * nt0;
        ht4.w = u1 * hv4.w + (1.0f - u1) * nt1;
    }
    if (wrp == 0) {   // ht output written once
        const size_t off_ht = (size_t)Bn * Nn * 2 + (size_t)Bn * Mn * Nn * 2;
        ((float4*)(out + off_ht))[(size_t)b * 32 + lane] = ht4;
    }

    // ---- matvec: this warp's 11 rows, dot(ht4, lv[k]) + shuffle reduce ----
    #pragma unroll
    for (int k = 0; k < 11; k++) {
        const int row = wrp * 11 + k;                // 6 warps x 11 covers 0..65
        if (row < Nn) {
            const float4 l = lv[k];
            float d = fmaf(l.x, ht4.x, fmaf(l.y, ht4.y, fmaf(l.z, ht4.z, l.w * ht4.w)));
            d += __shfl_xor_sync(0xffffffffu, d, 16);
            d += __shfl_xor_sync(0xffffffffu, d, 8);
            d += __shfl_xor_sync(0xffffffffu, d, 4);
            d += __shfl_xor_sync(0xffffffffu, d, 2);
            d += __shfl_xor_sync(0xffffffffu, d, 1);
            if (lane == 0) {
                const float c = (d + lin_b[row]) * alpha_t[b * Nn + row];
                s_coef2[row] = pack2(c, c);
            }
        }
    }
    __syncthreads();   // the ONLY barrier: orders emb stores + coef stores

    // ---- FIR: circular buffer, 6 rolled blocks x 11 unrolled ----
    const int p0 = tid * Cn;
    ull acc[Cn], P[Cn];
    #pragma unroll
    for (int i = 0; i < Cn; i++) {
        P[(Cn - i) % Cn] = s_exy[PAD + p0 + i];
        acc[i] = 0ULL;
    }
    #pragma unroll 1
    for (int blk = 0; blk < 6; blk++) {
        const int nb = blk * Cn;
        #pragma unroll
        for (int j = 0; j < Cn; j++) {
            const ull c2 = s_coef2[nb + j];          // broadcast (rows 64,65 zero)
            acc[10] = ffma2(c2, P[(j + 1) % Cn], acc[10]);
            P[(j + 1) % Cn] = s_exy[PAD + p0 - (nb + j) - 1];   // min idx = PAD-66 = 6
            #pragma unroll
            for (int i = 9; i >= 0; i--)
                acc[i] = ffma2(c2, P[(j - i + 22) % Cn], acc[i]);
        }
    }

    // ---- output assembly (q re-read = L1 hit; loaded by conv this launch) ----
    float2* st_out = (float2*)out + (size_t)b * Nn;
    float2* qt_out = (float2*)(out + (size_t)Bn * Nn * 2) + (size_t)b * Mn * Nn;
    #pragma unroll
    for (int i = 0; i < Cn; i++) {
        const int p = p0 + i;
        float fx, fy; unpack2(acc[i], fx, fy);
        float2 qv = make_float2(0.0f, 0.0f);
        if (p < Mn * Nn) qv = qf[p];                 // q_shift[j] = q_flat[j+N] = q_flat[p]
        float2 r = make_float2(qv.x + fx, qv.y + fy);
        if (p < Nn) st_out[p] = r;                   // st = q_row0 + f[:N]
        else        qt_out[p - Nn] = r;              // qt = q_shift + tail
    }
}

extern "C" void kernel_launch(void* const* d_in, const int* in_sizes, int n_in,
                              void* d_out, int out_size) {
    const float* qt1     = (const float*)d_in[0];
    const float* ht1     = (const float*)d_in[1];
    const float* zt      = (const float*)d_in[2];
    const float* alpha_t = (const float*)d_in[3];
    const float* conv_w  = (const float*)d_in[4];
    const float* conv_b  = (const float*)d_in[5];
    const float* W_xr    = (const float*)d_in[6];
    const float* W_hr    = (const float*)d_in[7];
    const float* b_r     = (const float*)d_in[8];
    const float* W_xu    = (const float*)d_in[9];
    const float* W_hu    = (const float*)d_in[10];
    const float* b_u     = (const float*)d_in[11];
    const float* W_xn    = (const float*)d_in[12];
    const float* W_hn    = (const float*)d_in[13];
    const float* b_n     = (const float*)d_in[14];
    const float* lin_w   = (const float*)d_in[15];
    const float* lin_b   = (const float*)d_in[16];
    const float* W_emb   = (const float*)d_in[17];

    gen_cell_kernel<<<Bn, NT>>>(qt1, ht1, zt, alpha_t, conv_w, conv_b,
                                W_xr, W_hr, b_r, W_xu, W_hu, b_u,
                                W_xn, W_hn, b_n, lin_w, lin_b, W_emb,
                                (float*)d_out);
}

// round 14
// speedup vs baseline: 1.1015x; 1.1015x over previous
#include <cuda_runtime.h>

// GeneratorCell: B=128, M=32 queue rows, N=64 strokes, K=2048 stroke length
// Converged design (R7 lineage): 1 CTA/batch, 192 threads, 3 phases:
//   phase0: emb staging + q tile stash + parallel conv partials (one DRAM wave)
//   phase1/2: GRU + coef matvec (lin_w preloaded, shuffle reduce)
//   phase3: FIR overlap-add, C=11 register sliding window, 1 LDS.64/iter
#define Bn 128
#define Mn 32
#define Nn 64
#define Kn 2048
#define NT 192                     // 6 warps, grid=128
#define Cn 11                      // consecutive p's per thread; 192*11 = 2112 = N + M*N
#define PAD 72                     // bottom zero pad (even, >=66 for prefetch reach)
#define EMB_SZ (PAD + Kn + 64)     // ull elements

typedef unsigned long long ull;

__device__ __forceinline__ float sigmoidf_(float x) { return 1.0f / (1.0f + __expf(-x)); }
__device__ __forceinline__ float tanhf_(float x) {   // fast tanh via MUFU exp (err ~1e-6)
    float e = __expf(2.0f * x);
    return 1.0f - 2.0f / (e + 1.0f);
}

__device__ __forceinline__ ull pack2(float x, float y) {
    ull r; asm("mov.b64 %0, {%1,%2};" : "=l"(r) : "f"(x), "f"(y)); return r;
}
__device__ __forceinline__ void unpack2(ull v, float& x, float& y) {
    asm("mov.b64 {%0,%1}, %2;" : "=f"(x), "=f"(y) : "l"(v));
}
__device__ __forceinline__ ull ffma2(ull a, ull b, ull c) {   // packed f32x2 FMA (sm_100+)
    ull d; asm("fma.rn.f32x2 %0, %1, %2, %3;" : "=l"(d) : "l"(a), "l"(b), "l"(c)); return d;
}

__global__ __launch_bounds__(NT) void gen_cell_kernel(
    const float* __restrict__ qt1,      // [B, M, N, 2]
    const float* __restrict__ ht1,      // [B, N, 2]
    const float* __restrict__ zt,       // [B, N]
    const float* __restrict__ alpha_t,  // [B, N]
    const float* __restrict__ conv_w,   // [2, 2, M+1, 1]
    const float* __restrict__ conv_b,   // [2]
    const float* __restrict__ W_xr, const float* __restrict__ W_hr, const float* __restrict__ b_r,
    const float* __restrict__ W_xu, const float* __restrict__ W_hu, const float* __restrict__ b_u,
    const float* __restrict__ W_xn, const float* __restrict__ W_hn, const float* __restrict__ b_n,
    const float* __restrict__ lin_w,    // [N, 2N]
    const float* __restrict__ lin_b,    // [N]
    const float* __restrict__ W_emb,    // [K, 2]
    float* __restrict__ out)            // st [B,N,2] | qt [B,M,N,2] | ht [B,N,2]
{
    __shared__ __align__(16) ull    s_exy[EMB_SZ];   // interleaved (x,y) emb, zero-padded
    __shared__ __align__(16) float2 s_q[Mn * Nn];    // full q tile, reused for output
    __shared__ float2 s_part[3 * Nn];                // conv partials [group][n]
    __shared__ ull    s_coef2[Nn];                   // (coef, coef) packed f32x2
    __shared__ __align__(16) float s_ht[2 * Nn];

    const int b    = blockIdx.x;
    const int tid  = threadIdx.x;
    const int lane = tid & 31;
    const int wrp  = tid >> 5;
    const float2* qf = (const float2*)(qt1 + (size_t)b * Mn * Nn * 2);

    // ============ phase 0: emb staging + q tile (reused) + conv partials ============
    {
        const float4* we4 = (const float4*)W_emb;   // 1024 float4 = 2048 (x,y) pairs
        float4 e0 = we4[tid],       e1 = we4[tid + 192], e2 = we4[tid + 384];
        float4 e3 = we4[tid + 576], e4 = we4[tid + 768];
        float4 e5 = make_float4(0.f, 0.f, 0.f, 0.f);
        if (tid < 64) e5 = we4[tid + 960];

        // conv input loads (tap h = g*11+k; tap 32 is the ht1 row)
        const int n = tid & 63;
        const int g = tid >> 6;
        float2 v[11];
        #pragma unroll
        for (int k = 0; k < 11; k++) {
            const int h = g * 11 + k;
            v[k] = (h < 32) ? qf[h * Nn + n] : ((const float2*)ht1)[b * Nn + n];
        }

        // zero the emb pads
        if (tid < PAD) s_exy[tid] = 0ULL;
        if (tid < 64)  s_exy[PAD + Kn + tid] = 0ULL;

        // staged emb store (interleaved, STS.128)
        float4* exy4 = (float4*)(s_exy + PAD);
        exy4[tid]       = e0;  exy4[tid + 192] = e1;  exy4[tid + 384] = e2;
        exy4[tid + 576] = e3;  exy4[tid + 768] = e4;
        if (tid < 64) exy4[tid + 960] = e5;

        // stash q tile for output assembly
        #pragma unroll
        for (int k = 0; k < 11; k++) {
            const int h = g * 11 + k;
            if (h < 32) s_q[h * Nn + n] = v[k];
        }

        // conv partial sums, dual chains
        float p0a = 0.f, p0b = 0.f, p1a = 0.f, p1b = 0.f;
        #pragma unroll
        for (int k = 0; k < 11; k++) {
            const int h = g * 11 + k;
            const float wa = conv_w[h],      wb = conv_w[33 + h];
            const float wc = conv_w[66 + h], wd = conv_w[99 + h];
            if (k & 1) {
                p0b = fmaf(v[k].x, wa, fmaf(v[k].y, wb, p0b));
                p1b = fmaf(v[k].x, wc, fmaf(v[k].y, wd, p1b));
            } else {
                p0a = fmaf(v[k].x, wa, fmaf(v[k].y, wb, p0a));
                p1a = fmaf(v[k].x, wc, fmaf(v[k].y, wd, p1a));
            }
        }
        s_part[g * Nn + n] = make_float2(p0a + p0b, p1a + p1b);
    }
    __syncthreads();

    // ---- preload lin_w row slices (LDG latency hides under GRU + window preload) ----
    float4 lv[11];
    {
        const float4* lw4 = (const float4*)lin_w;             // [64 rows][32 float4]
        #pragma unroll
        for (int k = 0; k < 11; k++) {
            const int row = wrp * 11 + k;
            lv[k] = (row < Nn) ? lw4[row * 32 + lane] : make_float4(0.f, 0.f, 0.f, 0.f);
        }
    }

    // ---- preload FIR window (depends only on s_exy): LDS latency hides under GRU ----
    const int p0 = tid * Cn;
    ull acc[Cn], w[Cn];
    #pragma unroll
    for (int i = 0; i < Cn; i++) {
        w[i] = s_exy[PAD + p0 + i];
        acc[i] = 0ULL;
    }
    ull nxt = s_exy[PAD + p0 - 1];

    // ============ phase 1: GRU per stroke (tid<64; short tail, fast tanh) ============
    if (tid < 64) {
        const int n = tid;
        const float2 hv = ((const float2*)ht1)[b * Nn + n];   // L1 hit
        const float2 pa = s_part[n], pb = s_part[Nn + n], pc = s_part[2 * Nn + n];
        const float h0 = (pa.x + pb.x) + pc.x + conv_b[0];    // ht1 tap already in pc
        const float h1 = (pa.y + pb.y) + pc.y + conv_b[1];

        const float x0 = zt[b * Nn + n];
        const float x1 = alpha_t[b * Nn + n];

        float r0 = sigmoidf_(fmaf(x0, W_xr[0], fmaf(x1, W_xr[2], fmaf(h0, W_hr[0], fmaf(h1, W_hr[2], b_r[0])))));
        float r1 = sigmoidf_(fmaf(x0, W_xr[1], fmaf(x1, W_xr[3], fmaf(h0, W_hr[1], fmaf(h1, W_hr[3], b_r[1])))));
        float u0 = sigmoidf_(fmaf(x0, W_xu[0], fmaf(x1, W_xu[2], fmaf(h0, W_hu[0], fmaf(h1, W_hu[2], b_u[0])))));
        float u1 = sigmoidf_(fmaf(x0, W_xu[1], fmaf(x1, W_xu[3], fmaf(h0, W_hu[1], fmaf(h1, W_hu[3], b_u[1])))));

        const float rh0 = r0 * h0, rh1 = r1 * h1;
        float nt0 = tanhf_(fmaf(x0, W_xn[0], fmaf(x1, W_xn[2], fmaf(rh0, W_hn[0], fmaf(rh1, W_hn[2], b_n[0])))));
        float nt1 = tanhf_(fmaf(x0, W_xn[1], fmaf(x1, W_xn[3], fmaf(rh0, W_hn[1], fmaf(rh1, W_hn[3], b_n[1])))));

        const float hn0 = u0 * hv.x + (1.0f - u0) * nt0;
        const float hn1 = u1 * hv.y + (1.0f - u1) * nt1;

        s_ht[2 * n + 0] = hn0;
        s_ht[2 * n + 1] = hn1;

        const size_t off_ht = (size_t)Bn * Nn * 2 + (size_t)Bn * Mn * Nn * 2;
        ((float2*)(out + off_ht))[(size_t)b * Nn + n] = make_float2(hn0, hn1);
    }
    __syncthreads();

    // ============ phase 2: coef matvec with preloaded lin_w + shuffle reduce ============
    {
        const float4 ht4 = ((const float4*)s_ht)[lane];       // per-lane slice of ht vector
        #pragma unroll
        for (int k = 0; k < 11; k++) {
            const int row = wrp * 11 + k;                     // 6 warps x 11 >= 64
            if (row < Nn) {
                const float4 l = lv[k];
                float d = fmaf(l.x, ht4.x, fmaf(l.y, ht4.y, fmaf(l.z, ht4.z, l.w * ht4.w)));
                d += __shfl_xor_sync(0xffffffffu, d, 16);
                d += __shfl_xor_sync(0xffffffffu, d, 8);
                d += __shfl_xor_sync(0xffffffffu, d, 4);
                d += __shfl_xor_sync(0xffffffffu, d, 2);
                d += __shfl_xor_sync(0xffffffffu, d, 1);
                if (lane == 0) {
                    const float c = (d + lin_b[row]) * alpha_t[b * Nn + row];
                    s_coef2[row] = pack2(c, c);
                }
            }
        }
    }
    __syncthreads();

    // ============ phase 3: FIR overlap-add, C=11 window, 1 LDS.64/iter + prefetch ======
    #pragma unroll
    for (int n = 0; n < Nn; n++) {
        const ull c2 = s_coef2[n];                 // warp-uniform broadcast
        #pragma unroll
        for (int i = 0; i < Cn; i++) acc[i] = ffma2(c2, w[i], acc[i]);
        #pragma unroll
        for (int i = Cn - 1; i > 0; i--) w[i] = w[i - 1];   // register renaming (full unroll)
        w[0] = nxt;
        nxt = s_exy[PAD + p0 - n - 2];             // prefetch (min idx = PAD-65 = 7 >= 0)
    }

    // ============ output assembly (q operands from shared) ============
    float2* st_out = (float2*)out + (size_t)b * Nn;
    float2* qt_out = (float2*)(out + (size_t)Bn * Nn * 2) + (size_t)b * Mn * Nn;
    #pragma unroll
    for (int i = 0; i < Cn; i++) {
        const int p = p0 + i;
        float fx, fy; unpack2(acc[i], fx, fy);
        float2 qv = make_float2(0.0f, 0.0f);
        if (p < Mn * Nn) qv = s_q[p];              // q_shift[j] = q_flat[j+N] = q_flat[p]
        float2 r = make_float2(qv.x + fx, qv.y + fy);
        if (p < Nn) st_out[p] = r;                 // st = q_row0 + f[:N]
        else        qt_out[p - Nn] = r;            // qt = q_shift + tail
    }
}

extern "C" void kernel_launch(void* const* d_in, const int* in_sizes, int n_in,
                              void* d_out, int out_size) {
    const float* qt1     = (const float*)d_in[0];
    const float* ht1     = (const float*)d_in[1];
    const float* zt      = (const float*)d_in[2];
    const float* alpha_t = (const float*)d_in[3];
    const float* conv_w  = (const float*)d_in[4];
    const float* conv_b  = (const float*)d_in[5];
    const float* W_xr    = (const float*)d_in[6];
    const float* W_hr    = (const float*)d_in[7];
    const float* b_r     = (const float*)d_in[8];
    const float* W_xu    = (const float*)d_in[9];
    const float* W_hu    = (const float*)d_in[10];
    const float* b_u     = (const float*)d_in[11];
    const float* W_xn    = (const float*)d_in[12];
    const float* W_hn    = (const float*)d_in[13];
    const float* b_n     = (const float*)d_in[14];
    const float* lin_w   = (const float*)d_in[15];
    const float* lin_b   = (const float*)d_in[16];
    const float* W_emb   = (const float*)d_in[17];

    gen_cell_kernel<<<Bn, NT>>>(qt1, ht1, zt, alpha_t, conv_w, conv_b,
                                W_xr, W_hr, b_r, W_xu, W_hu, b_u,
                                W_xn, W_hn, b_n, lin_w, lin_b, W_emb,
                                (float*)d_out);
}